// round 2
// baseline (speedup 1.0000x reference)
#include <cuda_runtime.h>

#define TPB 128
#define NC  17
typedef unsigned long long ull;

// ---------------------------------------------------------------------------
// f32x2 packed helpers
// ---------------------------------------------------------------------------
__device__ __forceinline__ ull pk2(float lo, float hi) {
    ull r; asm("mov.b64 %0, {%1, %2};" : "=l"(r) : "f"(lo), "f"(hi)); return r;
}
__device__ __forceinline__ void unpk2(ull v, float& lo, float& hi) {
    asm("mov.b64 {%0, %1}, %2;" : "=f"(lo), "=f"(hi) : "l"(v));
}
__device__ __forceinline__ ull ffma2(ull a, ull b, ull c) {
    ull d; asm("fma.rn.f32x2 %0, %1, %2, %3;" : "=l"(d) : "l"(a), "l"(b), "l"(c)); return d;
}
__device__ __forceinline__ ull fmul2(ull a, ull b) {
    ull d; asm("mul.rn.f32x2 %0, %1, %2;" : "=l"(d) : "l"(a), "l"(b)); return d;
}
__device__ __forceinline__ ull fadd2(ull a, ull b) {
    ull d; asm("add.rn.f32x2 %0, %1, %2;" : "=l"(d) : "l"(a), "l"(b)); return d;
}

// theta slice per circuit: A->theta[0], B->theta[3], C->theta[4], D->theta[1], E->theta[2][0]
__device__ __forceinline__ int circ_slice(int c) {
    if (c < 4)  return c;            // stage A
    if (c < 8)  return 12 + (c - 4); // stage B
    if (c < 12) return 16 + (c - 8); // stage C
    if (c < 16) return 4 + (c - 12); // stage D
    return 8;                        // stage E
}

// Build one 16x16 unitary column (basis column `col`) of circuit c's SEL block.
__device__ __forceinline__ void build_col(const float* __restrict__ w, int col,
                                          float2* __restrict__ Wout) {
    float sr[16], si[16];
#pragma unroll
    for (int i = 0; i < 16; i++) { sr[i] = (i == col) ? 1.f : 0.f; si[i] = 0.f; }
#pragma unroll
    for (int l = 0; l < 4; l++) {
#pragma unroll
        for (int q = 0; q < 4; q++) {
            const float phi = w[(l * 4 + q) * 3 + 0];
            const float th  = w[(l * 4 + q) * 3 + 1];
            const float om  = w[(l * 4 + q) * 3 + 2];
            float ch, sh, ca, sa, cb, sb;
            __sincosf(0.5f * th, &sh, &ch);
            __sincosf(0.5f * (phi + om), &sa, &ca);
            __sincosf(0.5f * (phi - om), &sb, &cb);
            const float u00r =  ca * ch, u00i = -sa * ch;
            const float u01r = -cb * sh, u01i = -sb * sh;
            const float u10r =  cb * sh, u10i = -sb * sh;
            const float u11r =  ca * ch, u11i =  sa * ch;
            const int mask = 8 >> q;
#pragma unroll
            for (int k = 0; k < 16; k++) {
                if (k & mask) continue;
                const int k1 = k | mask;
                float ar = sr[k],  ai = si[k];
                float br = sr[k1], bi = si[k1];
                sr[k]  = u00r * ar - u00i * ai + u01r * br - u01i * bi;
                si[k]  = u00r * ai + u00i * ar + u01r * bi + u01i * br;
                sr[k1] = u10r * ar - u10i * ai + u11r * br - u11i * bi;
                si[k1] = u10r * ai + u10i * ar + u11r * bi + u11i * br;
            }
        }
        const int r = (l % 3) + 1;
#pragma unroll
        for (int q = 0; q < 4; q++) {
            const int cm = 8 >> q;
            const int tm = 8 >> ((q + r) & 3);
#pragma unroll
            for (int k = 0; k < 16; k++) {
                if ((k & cm) && !(k & tm)) {
                    const int k1 = k | tm;
                    float tr = sr[k], ti = si[k];
                    sr[k] = sr[k1]; si[k] = si[k1];
                    sr[k1] = tr;    si[k1] = ti;
                }
            }
        }
    }
#pragma unroll
    for (int k = 0; k < 16; k++) Wout[k * 16 + col] = make_float2(sr[k], si[k]);
}

// Walsh tree: p[16] -> 4 signed sums (qubit 0 = MSB of k)
__device__ __forceinline__ void wht4(const float* p, float* o) {
    float a[8], aa[4];
    float e3 = 0.f, e2 = 0.f;
#pragma unroll
    for (int j = 0; j < 8; j++) { a[j] = p[2 * j] + p[2 * j + 1]; e3 += p[2 * j] - p[2 * j + 1]; }
#pragma unroll
    for (int m = 0; m < 4; m++) { aa[m] = a[2 * m] + a[2 * m + 1]; e2 += a[2 * m] - a[2 * m + 1]; }
    o[0] = (aa[0] + aa[1]) - (aa[2] + aa[3]);
    o[1] = (aa[0] - aa[1]) + (aa[2] - aa[3]);
    o[2] = e2;
    o[3] = e3;
}

__device__ __forceinline__ void emb2(float a0, float a1, float* u) {
    float s0, c0, s1, c1;
    __sincosf(0.5f * a0, &s0, &c0);
    __sincosf(0.5f * a1, &s1, &c1);
    u[0] = c0 * c1; u[1] = c0 * s1; u[2] = s0 * c1; u[3] = s0 * s1;
}

// Full circuit, 4 expvals. W = packed complex rows [k][j].
__device__ __forceinline__ void run4_full(const ull* __restrict__ W,
                                          float a0, float a1, float a2, float a3,
                                          float* o) {
    float u[4], v[4];
    emb2(a0, a1, u); emb2(a2, a3, v);
    ull pp[16];
#pragma unroll
    for (int i = 0; i < 4; i++)
#pragma unroll
        for (int j = 0; j < 4; j++) { const float t = u[i] * v[j]; pp[i * 4 + j] = pk2(t, t); }
    float p[16];
#pragma unroll
    for (int k = 0; k < 16; k++) {
        const ulonglong2* row = (const ulonglong2*)(W + k * 16);
        ull ac[4] = {0ull, 0ull, 0ull, 0ull};
#pragma unroll
        for (int jj = 0; jj < 8; jj++) {
            const ulonglong2 w2 = row[jj];
            ac[jj & 1]       = ffma2(w2.x, pp[2 * jj],     ac[jj & 1]);
            ac[2 + (jj & 1)] = ffma2(w2.y, pp[2 * jj + 1], ac[2 + (jj & 1)]);
        }
        ull s = fadd2(fadd2(ac[0], ac[1]), fadd2(ac[2], ac[3]));
        float yr, yi; unpk2(s, yr, yi);
        p[k] = fmaf(yr, yr, yi * yi);
    }
    wht4(p, o);
}

// a0 == 0 : only columns 0..7 active (amp over qubit1 x qubits2,3)
__device__ __forceinline__ void run4_half(const ull* __restrict__ W,
                                          float a1, float a2, float a3, float* o) {
    float s1, c1, v[4];
    __sincosf(0.5f * a1, &s1, &c1);
    emb2(a2, a3, v);
    ull pp[8];
#pragma unroll
    for (int j = 0; j < 4; j++) {
        float t0 = c1 * v[j], t1 = s1 * v[j];
        pp[j] = pk2(t0, t0); pp[4 + j] = pk2(t1, t1);
    }
    float p[16];
#pragma unroll
    for (int k = 0; k < 16; k++) {
        const ulonglong2* row = (const ulonglong2*)(W + k * 16);
        ull a0c = 0ull, a1c = 0ull;
#pragma unroll
        for (int jj = 0; jj < 4; jj++) {
            const ulonglong2 w2 = row[jj];
            a0c = ffma2(w2.x, pp[2 * jj],     a0c);
            a1c = ffma2(w2.y, pp[2 * jj + 1], a1c);
        }
        ull s = fadd2(a0c, a1c);
        float yr, yi; unpk2(s, yr, yi);
        p[k] = fmaf(yr, yr, yi * yi);
    }
    wht4(p, o);
}

// a2 == a3 == 0 : only columns {0,4,8,12} active with amplitudes u[i]
__device__ __forceinline__ void run4_sparse(const ull* __restrict__ W,
                                            float a0, float a1, float* o) {
    float u[4];
    emb2(a0, a1, u);
    ull pu[4];
#pragma unroll
    for (int i = 0; i < 4; i++) pu[i] = pk2(u[i], u[i]);
    float p[16];
#pragma unroll
    for (int k = 0; k < 16; k++) {
        const ull* row = W + k * 16;
        ull a0c = fmul2(row[0], pu[0]);
        ull a1c = fmul2(row[4], pu[1]);
        a0c = ffma2(row[8],  pu[2], a0c);
        a1c = ffma2(row[12], pu[3], a1c);
        ull s = fadd2(a0c, a1c);
        float yr, yi; unpk2(s, yr, yi);
        p[k] = fmaf(yr, yr, yi * yi);
    }
    wht4(p, o);
}

// Single expval via real quadratic form e = psi^T M psi (sign baked into M).
__device__ __forceinline__ float run1(const float* __restrict__ M,
                                      float a0, float a1, float a2, float a3) {
    float u[4], v[4];
    emb2(a0, a1, u); emb2(a2, a3, v);
    float psi[16];
#pragma unroll
    for (int i = 0; i < 4; i++)
#pragma unroll
        for (int j = 0; j < 4; j++) psi[i * 4 + j] = u[i] * v[j];
    ull pj[8];
#pragma unroll
    for (int j = 0; j < 8; j++) pj[j] = pk2(psi[2 * j], psi[2 * j + 1]);
    float e = 0.f;
#pragma unroll
    for (int k = 0; k < 16; k++) {
        const ulonglong2* row = (const ulonglong2*)(M + k * 16);
        ull a0c = 0ull, a1c = 0ull;
#pragma unroll
        for (int i = 0; i < 4; i++) {
            const ulonglong2 m2 = row[i];
            a0c = ffma2(m2.x, pj[2 * i],     a0c);
            a1c = ffma2(m2.y, pj[2 * i + 1], a1c);
        }
        ull s = fadd2(a0c, a1c);
        float lo, hi; unpk2(s, lo, hi);
        e = fmaf(psi[k], lo + hi, e);
    }
    return e;
}

// ---------------------------------------------------------------------------
// Fused kernel: per-block cooperative W/M build in smem, then per-thread batch.
// ---------------------------------------------------------------------------
__global__ __launch_bounds__(TPB)
void vqc_fused(const float* __restrict__ x, const float* __restrict__ theta,
               float* __restrict__ out, int B) {
    __shared__ __align__(16) float2 sW[NC * 256];   // 34 KB
    __shared__ __align__(16) float  sM[5 * 256];    // 5 KB
    const int tid = threadIdx.x;

    // Phase 1: build 17 unitaries (272 column tasks over 128 threads)
    for (int t = tid; t < NC * 16; t += TPB) {
        const int c = t >> 4, col = t & 15;
        build_col(theta + circ_slice(c) * 48, col, &sW[c * 256]);
    }
    __syncthreads();

    // Phase 2: quadratic-form matrices for the 5 single-output circuits (12..16)
    for (int t = tid; t < 80; t += TPB) {
        const int c5 = t >> 4, r = t & 15;
        const float2* Wc = &sW[(12 + c5) * 256];
        float m[16];
#pragma unroll
        for (int j = 0; j < 16; j++) m[j] = 0.f;
#pragma unroll
        for (int k = 0; k < 16; k++) {
            const float2 wr = Wc[k * 16 + r];
#pragma unroll
            for (int j = 0; j < 16; j++) {
                const float2 wj = Wc[k * 16 + j];
                const float tt = wr.x * wj.x + wr.y * wj.y;
                m[j] = (k & 8) ? (m[j] - tt) : (m[j] + tt);
            }
        }
#pragma unroll
        for (int j = 0; j < 16; j++) sM[c5 * 256 + r * 16 + j] = m[j];
    }
    __syncthreads();

    const int b = blockIdx.x * TPB + tid;
    if (b >= B) return;

    float H[16], Hn[16], H4[4];
#pragma unroll
    for (int i = 0; i < 13; i++) H[1 + i] = x[b * 13 + i];

    const ull* Wu = (const ull*)sW;
    // Stage A (H[0]=0 -> half; H[14]=H[15]=0 -> sparse)
    run4_half  (Wu + 0 * 256, H[1], H[2], H[3], &Hn[0]);
    run4_full  (Wu + 1 * 256, H[4], H[5], H[6], H[7],  &Hn[4]);
    run4_full  (Wu + 2 * 256, H[8], H[9], H[10], H[11], &Hn[8]);
    run4_sparse(Wu + 3 * 256, H[12], H[13], &Hn[12]);
    // Stage B (transposed wiring) Hn -> H
#pragma unroll
    for (int j = 0; j < 4; j++)
        run4_full(Wu + (4 + j) * 256, Hn[j], Hn[4 + j], Hn[8 + j], Hn[12 + j], &H[4 * j]);
    // Stage C: H -> Hn
#pragma unroll
    for (int j = 0; j < 4; j++)
        run4_full(Wu + (8 + j) * 256, H[j], H[4 + j], H[8 + j], H[12 + j], &Hn[4 * j]);
    // Stage D: 16 -> 4 (quadratic forms)
#pragma unroll
    for (int j = 0; j < 4; j++)
        H4[j] = run1(sM + j * 256, Hn[j], Hn[4 + j], Hn[8 + j], Hn[12 + j]);
    // Stage E: 4 -> 1
    const float o = run1(sM + 4 * 256, H4[0], H4[1], H4[2], H4[3]);

    out[b] = o * (float)(3.141592653589793 - 1.1920928955078125e-7);
}

extern "C" void kernel_launch(void* const* d_in, const int* in_sizes, int n_in,
                              void* d_out, int out_size) {
    const float* x     = (const float*)d_in[0];
    const float* theta = (const float*)d_in[1];
    if (n_in >= 2 && in_sizes[0] < in_sizes[1]) {
        x     = (const float*)d_in[1];
        theta = (const float*)d_in[0];
    }
    float* out = (float*)d_out;
    const int B = out_size;
    vqc_fused<<<(B + TPB - 1) / TPB, TPB>>>(x, theta, out, B);
}